// round 10
// baseline (speedup 1.0000x reference)
#include <cuda_runtime.h>
#include <cuda_bf16.h>
#include <math.h>
#include <stdint.h>

#define NN 50000
#define NE 800000
#define NH0 25000          // row-split for pipelined junctions
#define NH1 (NN - NH0)

// ---------------- scratch (device globals; allocation-free rule) -----------
__device__ float g_bufA[NN * 64];
__device__ float g_bufB[NN * 64];
__device__ float g_bufC[NN * 64];
__device__ int   g_cnt[NN];
__device__ int   g_start[NN];
__device__ int   g_woff[NN];
__device__ int   g_total;
__device__ int2  g_edge[NE];   // packed (col, weight-bits)

// ---------------------------------------------------------------------------
// CSR build (order-free segment placement: per-block scan + global cursor)
// ---------------------------------------------------------------------------
__global__ void zero_cnt_kernel() {
    int i = blockIdx.x * blockDim.x + threadIdx.x;
    if (i < NN) g_cnt[i] = 0;
    if (i == 0) g_total = 0;
}

// 4 edges per thread: int4 coalesced load, 4 independent atomic chains
__global__ void hist_kernel(const int4* __restrict__ row4) {
    int i = blockIdx.x * blockDim.x + threadIdx.x;
    if (i < NE / 4) {
        int4 r = row4[i];
        atomicAdd(&g_cnt[r.x], 1);
        atomicAdd(&g_cnt[r.y], 1);
        atomicAdd(&g_cnt[r.z], 1);
        atomicAdd(&g_cnt[r.w], 1);
    }
}

__global__ __launch_bounds__(256) void offsets_kernel() {
    __shared__ int sp[256];
    __shared__ int base;
    const int t = threadIdx.x;
    const int r = blockIdx.x * 256 + t;
    int c = (r < NN) ? g_cnt[r] : 0;
    sp[t] = c;
    __syncthreads();
    #pragma unroll
    for (int off = 1; off < 256; off <<= 1) {
        int v = (t >= off) ? sp[t - off] : 0;
        __syncthreads();
        sp[t] += v;
        __syncthreads();
    }
    if (t == 255) base = atomicAdd(&g_total, sp[255]);
    __syncthreads();
    if (r < NN) {
        int s = base + sp[t] - c;
        g_start[r] = s;
        g_woff[r]  = s;
    }
}

// 4 edges per thread: vector loads, 4 independent atomic+write chains
__global__ void scatter_kernel(const int4* __restrict__ row4,
                               const int4* __restrict__ col4,
                               const float4* __restrict__ ew4) {
    int i = blockIdx.x * blockDim.x + threadIdx.x;
    if (i < NE / 4) {
        int4 r = row4[i];
        int4 c = col4[i];
        float4 w = ew4[i];
        int p0 = atomicAdd(&g_woff[r.x], 1);
        int p1 = atomicAdd(&g_woff[r.y], 1);
        int p2 = atomicAdd(&g_woff[r.z], 1);
        int p3 = atomicAdd(&g_woff[r.w], 1);
        g_edge[p0] = make_int2(c.x, __float_as_int(w.x));
        g_edge[p1] = make_int2(c.y, __float_as_int(w.y));
        g_edge[p2] = make_int2(c.z, __float_as_int(w.z));
        g_edge[p3] = make_int2(c.w, __float_as_int(w.w));
    }
}

// ---------------------------------------------------------------------------
// SpMM via CSR, warp per row, row range [rowBase, rowBase+rowCnt).
// NF2 = feature float2s per row (32 for D=64, 20 for D=40).
// LOGSM: fuse log-softmax over D=40 into the epilogue (writes final output).
// ---------------------------------------------------------------------------
template <int NF2, bool LOGSM>
__global__ __launch_bounds__(256) void spmm_csr_kernel(
    const float2* __restrict__ sup, float2* __restrict__ out,
    int rowBase, int rowCnt)
{
    int w = (blockIdx.x * blockDim.x + threadIdx.x) >> 5;
    if (w >= rowCnt) return;
    int warp = rowBase + w;
    const int lane = threadIdx.x & 31;
    const bool act = (NF2 == 32) || (lane < NF2);
    int s = g_start[warp];
    int e = s + g_cnt[warp];

    float2 acc = make_float2(0.f, 0.f);
    int i = s;
    for (; i + 4 <= e; i += 4) {
        int2 c0 = g_edge[i + 0];
        int2 c1 = g_edge[i + 1];
        int2 c2 = g_edge[i + 2];
        int2 c3 = g_edge[i + 3];
        if (act) {
            float2 v0 = sup[(size_t)c0.x * NF2 + lane];
            float2 v1 = sup[(size_t)c1.x * NF2 + lane];
            float2 v2 = sup[(size_t)c2.x * NF2 + lane];
            float2 v3 = sup[(size_t)c3.x * NF2 + lane];
            float w0 = __int_as_float(c0.y), w1 = __int_as_float(c1.y);
            float w2 = __int_as_float(c2.y), w3 = __int_as_float(c3.y);
            acc.x = fmaf(v0.x, w0, acc.x); acc.y = fmaf(v0.y, w0, acc.y);
            acc.x = fmaf(v1.x, w1, acc.x); acc.y = fmaf(v1.y, w1, acc.y);
            acc.x = fmaf(v2.x, w2, acc.x); acc.y = fmaf(v2.y, w2, acc.y);
            acc.x = fmaf(v3.x, w3, acc.x); acc.y = fmaf(v3.y, w3, acc.y);
        }
    }
    for (; i < e; i++) {
        int2 c = g_edge[i];
        if (act) {
            float2 v = sup[(size_t)c.x * NF2 + lane];
            float ww = __int_as_float(c.y);
            acc.x = fmaf(v.x, ww, acc.x);
            acc.y = fmaf(v.y, ww, acc.y);
        }
    }

    if (!LOGSM) {
        if (act) out[(size_t)warp * NF2 + lane] = acc;
    } else {
        float mv = act ? fmaxf(acc.x, acc.y) : -INFINITY;
        #pragma unroll
        for (int o = 16; o; o >>= 1) mv = fmaxf(mv, __shfl_xor_sync(0xffffffffu, mv, o));
        float sv = act ? (expf(acc.x - mv) + expf(acc.y - mv)) : 0.f;
        #pragma unroll
        for (int o = 16; o; o >>= 1) sv += __shfl_xor_sync(0xffffffffu, sv, o);
        float ls = mv + logf(sv);
        if (act) out[(size_t)warp * NF2 + lane] = make_float2(acc.x - ls, acc.y - ls);
    }
}

// ---------------------------------------------------------------------------
// Split-bf16 tensor-core GEMM (rel_err ~2e-6)
// ---------------------------------------------------------------------------
#define SROW 24

__device__ __forceinline__ unsigned pack_bf16(float a, float b) {
    __nv_bfloat162 t = __floats2bfloat162_rn(a, b);
    return *reinterpret_cast<unsigned*>(&t);
}

__device__ __forceinline__ void mma16816(float* c, const unsigned* a, const unsigned* b) {
    asm volatile(
        "mma.sync.aligned.m16n8k16.row.col.f32.bf16.bf16.f32 "
        "{%0,%1,%2,%3}, {%4,%5,%6,%7}, {%8,%9}, {%0,%1,%2,%3};"
        : "+f"(c[0]), "+f"(c[1]), "+f"(c[2]), "+f"(c[3])
        : "r"(a[0]), "r"(a[1]), "r"(a[2]), "r"(a[3]), "r"(b[0]), "r"(b[1]));
}

template <bool RELU>
__global__ __launch_bounds__(256) void gemm_mma_kernel(
    const float* __restrict__ A, const float* __restrict__ B,
    const float* __restrict__ bias, float* __restrict__ C,
    int M, int K, int N)
{
    __shared__ __nv_bfloat16 Ah[2][128 * SROW], Al[2][128 * SROW];
    __shared__ __nv_bfloat16 Bh[2][64 * SROW],  Bl[2][64 * SROW];

    const int tid  = threadIdx.x;
    const int m0   = blockIdx.x * 128;
    const int wid  = tid >> 5;
    const int lane = tid & 31;
    const int wm = (wid & 3) * 32;
    const int wn = (wid >> 2) * 32;
    const int qm = lane >> 2;
    const int qk = lane & 3;

    const int arow = tid >> 1;
    const int akh  = (tid & 1) * 8;
    const bool aok = (m0 + arow) < M;
    const float* Aptr = A + (size_t)(m0 + arow) * K + akh;

    const int bk = tid >> 4;
    const int bn = (tid * 4) & 63;

    float av[8];
    float bv[4];
    float acc[2][4][4] = {};

    const int S = K / 16;

    auto load_regs = [&](int k0) {
        if (aok) {
            float4 v0 = *reinterpret_cast<const float4*>(Aptr + k0);
            float4 v1 = *reinterpret_cast<const float4*>(Aptr + k0 + 4);
            av[0] = v0.x; av[1] = v0.y; av[2] = v0.z; av[3] = v0.w;
            av[4] = v1.x; av[5] = v1.y; av[6] = v1.z; av[7] = v1.w;
            if (RELU) {
                #pragma unroll
                for (int i = 0; i < 8; i++) av[i] = fmaxf(av[i], 0.f);
            }
        } else {
            #pragma unroll
            for (int i = 0; i < 8; i++) av[i] = 0.f;
        }
        #pragma unroll
        for (int j = 0; j < 4; j++) {
            int n = bn + j;
            bv[j] = (n < N) ? B[(size_t)(k0 + bk) * N + n] : 0.f;
        }
    };

    auto store_stage = [&](int st) {
        float lo[8];
        unsigned h[4], l[4];
        #pragma unroll
        for (int i = 0; i < 8; i++) {
            __nv_bfloat16 hb = __float2bfloat16_rn(av[i]);
            lo[i] = av[i] - __bfloat162float(hb);
        }
        #pragma unroll
        for (int p = 0; p < 4; p++) {
            h[p] = pack_bf16(av[2 * p], av[2 * p + 1]);
            l[p] = pack_bf16(lo[2 * p], lo[2 * p + 1]);
        }
        *reinterpret_cast<uint4*>(&Ah[st][arow * SROW + akh]) = make_uint4(h[0], h[1], h[2], h[3]);
        *reinterpret_cast<uint4*>(&Al[st][arow * SROW + akh]) = make_uint4(l[0], l[1], l[2], l[3]);
        #pragma unroll
        for (int j = 0; j < 4; j++) {
            __nv_bfloat16 hb = __float2bfloat16_rn(bv[j]);
            float lf = bv[j] - __bfloat162float(hb);
            Bh[st][(bn + j) * SROW + bk] = hb;
            Bl[st][(bn + j) * SROW + bk] = __float2bfloat16_rn(lf);
        }
    };

    load_regs(0);
    store_stage(0);
    __syncthreads();

    for (int s = 0; s < S; s++) {
        const int cur = s & 1;
        if (s + 1 < S) load_regs((s + 1) * 16);

        unsigned ah[2][4], al[2][4], bh[4][2], bl[4][2];
        #pragma unroll
        for (int i = 0; i < 2; i++) {
            int r = (wm + i * 16 + qm) * SROW;
            ah[i][0] = *reinterpret_cast<unsigned*>(&Ah[cur][r + qk * 2]);
            ah[i][1] = *reinterpret_cast<unsigned*>(&Ah[cur][r + 8 * SROW + qk * 2]);
            ah[i][2] = *reinterpret_cast<unsigned*>(&Ah[cur][r + 8 + qk * 2]);
            ah[i][3] = *reinterpret_cast<unsigned*>(&Ah[cur][r + 8 * SROW + 8 + qk * 2]);
            al[i][0] = *reinterpret_cast<unsigned*>(&Al[cur][r + qk * 2]);
            al[i][1] = *reinterpret_cast<unsigned*>(&Al[cur][r + 8 * SROW + qk * 2]);
            al[i][2] = *reinterpret_cast<unsigned*>(&Al[cur][r + 8 + qk * 2]);
            al[i][3] = *reinterpret_cast<unsigned*>(&Al[cur][r + 8 * SROW + 8 + qk * 2]);
        }
        #pragma unroll
        for (int j = 0; j < 4; j++) {
            int r = (wn + j * 8 + qm) * SROW;
            bh[j][0] = *reinterpret_cast<unsigned*>(&Bh[cur][r + qk * 2]);
            bh[j][1] = *reinterpret_cast<unsigned*>(&Bh[cur][r + 8 + qk * 2]);
            bl[j][0] = *reinterpret_cast<unsigned*>(&Bl[cur][r + qk * 2]);
            bl[j][1] = *reinterpret_cast<unsigned*>(&Bl[cur][r + 8 + qk * 2]);
        }

        #pragma unroll
        for (int i = 0; i < 2; i++)
            #pragma unroll
            for (int j = 0; j < 4; j++) {
                mma16816(acc[i][j], ah[i], bh[j]);
                mma16816(acc[i][j], ah[i], bl[j]);
                mma16816(acc[i][j], al[i], bh[j]);
            }

        if (s + 1 < S) {
            store_stage(cur ^ 1);
            __syncthreads();
        }
    }

    #pragma unroll
    for (int j = 0; j < 4; j++) {
        int c0 = wn + j * 8 + (lane & 3) * 2;
        if (c0 >= N) continue;
        float b0 = bias[c0], b1 = bias[c0 + 1];
        #pragma unroll
        for (int i = 0; i < 2; i++) {
            int r0 = m0 + wm + i * 16 + (lane >> 2);
            if (r0 < M) {
                float2 o = make_float2(acc[i][j][0] + b0, acc[i][j][1] + b1);
                *reinterpret_cast<float2*>(C + (size_t)r0 * N + c0) = o;
            }
            if (r0 + 8 < M) {
                float2 o = make_float2(acc[i][j][2] + b0, acc[i][j][3] + b1);
                *reinterpret_cast<float2*>(C + (size_t)(r0 + 8) * N + c0) = o;
            }
        }
    }
}

// ---------------------------------------------------------------------------
// launch. Buffer chain (race-free under junction overlap):
//   gemm1 -> A ; spmm1: A -> B ; gemm2: B -> C ; spmm2: C -> B ;
//   gemm3: B -> A ; spmm3+lsm: A -> out
// Overlapped pairs only ever write buffers the concurrent spmm never reads.
// ---------------------------------------------------------------------------
extern "C" void kernel_launch(void* const* d_in, const int* in_sizes, int n_in,
                              void* d_out, int out_size)
{
    const float* x   = (const float*)d_in[0];
    const float* ew  = (const float*)d_in[1];
    const float* W1  = (const float*)d_in[2];
    const float* b1  = (const float*)d_in[3];
    const float* W2  = (const float*)d_in[4];
    const float* b2  = (const float*)d_in[5];
    const float* W3  = (const float*)d_in[6];
    const float* b3  = (const float*)d_in[7];
    const int*   row = (const int*)d_in[8];
    const int*   col = (const int*)d_in[9];
    float* out = (float*)d_out;

    float *bufA, *bufB, *bufC;
    cudaGetSymbolAddress((void**)&bufA, g_bufA);
    cudaGetSymbolAddress((void**)&bufB, g_bufB);
    cudaGetSymbolAddress((void**)&bufC, g_bufC);

    const int gemmBlocksF = (NN + 127) / 128;
    const int gemmBlocksH = (NH0 + 127) / 128;
    const int e4Blocks    = (NE / 4 + 255) / 256;
    const int rowBlocks   = (NN + 255) / 256;
    const int spmmBlocksH = (NH0 * 32 + 255) / 256;

    cudaStream_t s2;
    cudaStreamCreate(&s2);
    cudaEvent_t evFork, evCSR, evS1, evG2, evS2, evG3, evS3f, evEnd;
    cudaEventCreateWithFlags(&evFork, cudaEventDisableTiming);
    cudaEventCreateWithFlags(&evCSR,  cudaEventDisableTiming);
    cudaEventCreateWithFlags(&evS1,   cudaEventDisableTiming);
    cudaEventCreateWithFlags(&evG2,   cudaEventDisableTiming);
    cudaEventCreateWithFlags(&evS2,   cudaEventDisableTiming);
    cudaEventCreateWithFlags(&evG3,   cudaEventDisableTiming);
    cudaEventCreateWithFlags(&evS3f,  cudaEventDisableTiming);
    cudaEventCreateWithFlags(&evEnd,  cudaEventDisableTiming);

    cudaEventRecord(evFork, 0);
    cudaStreamWaitEvent(s2, evFork, 0);

    // s2: CSR build (concurrent with GEMM1 on main)
    zero_cnt_kernel<<<rowBlocks, 256, 0, s2>>>();
    hist_kernel<<<e4Blocks, 256, 0, s2>>>((const int4*)row);
    offsets_kernel<<<rowBlocks, 256, 0, s2>>>();
    scatter_kernel<<<e4Blocks, 256, 0, s2>>>((const int4*)row, (const int4*)col,
                                             (const float4*)ew);
    cudaEventRecord(evCSR, s2);

    // main: GEMM1 -> A
    gemm_mma_kernel<false><<<gemmBlocksF, 256>>>(x, W1, b1, bufA, NN, 512, 64);
    cudaStreamWaitEvent(0, evCSR, 0);

    // ---- layer 1: spmm1 A->B (split) ----
    spmm_csr_kernel<32, false><<<spmmBlocksH, 256>>>((const float2*)bufA, (float2*)bufB, 0, NH0);
    cudaEventRecord(evS1, 0);
    spmm_csr_kernel<32, false><<<spmmBlocksH, 256>>>((const float2*)bufA, (float2*)bufB, NH0, NH1);

    // s2: gemm2(H0) B->C overlaps spmm1(H1) (reads A, writes B[H1]) — disjoint
    cudaStreamWaitEvent(s2, evS1, 0);
    gemm_mma_kernel<true><<<gemmBlocksH, 256, 0, s2>>>(bufB, W2, b2, bufC, NH0, 64, 64);
    // main: gemm2(H1) B->C
    gemm_mma_kernel<true><<<gemmBlocksH, 256>>>(bufB + (size_t)NH0 * 64, W2, b2,
                                                bufC + (size_t)NH0 * 64, NH1, 64, 64);
    cudaEventRecord(evG2, s2);
    cudaStreamWaitEvent(0, evG2, 0);   // spmm2 gathers from all of C

    // ---- layer 2: spmm2 C->B (split) ----
    spmm_csr_kernel<32, false><<<spmmBlocksH, 256>>>((const float2*)bufC, (float2*)bufB, 0, NH0);
    cudaEventRecord(evS2, 0);
    spmm_csr_kernel<32, false><<<spmmBlocksH, 256>>>((const float2*)bufC, (float2*)bufB, NH0, NH1);

    // s2: gemm3(H0) B->A overlaps spmm2(H1) (reads C, writes B[H1]) — disjoint
    cudaStreamWaitEvent(s2, evS2, 0);
    gemm_mma_kernel<false><<<gemmBlocksH, 256, 0, s2>>>(bufB, W3, b3, bufA, NH0, 64, 40);
    // main: gemm3(H1) B->A
    gemm_mma_kernel<false><<<gemmBlocksH, 256>>>(bufB + (size_t)NH0 * 64, W3, b3,
                                                 bufA + (size_t)NH0 * 40, NH1, 64, 40);
    cudaEventRecord(evG3, s2);
    cudaStreamWaitEvent(0, evG3, 0);   // spmm3 gathers from all of A

    // ---- layer 3: spmm3 + fused log-softmax A->out, halves on both streams ----
    spmm_csr_kernel<20, true><<<spmmBlocksH, 256>>>((const float2*)bufA, (float2*)out, 0, NH0);
    cudaEventRecord(evS3f, 0);
    cudaStreamWaitEvent(s2, evS3f, 0);
    spmm_csr_kernel<20, true><<<spmmBlocksH, 256, 0, s2>>>((const float2*)bufA, (float2*)out, NH0, NH1);
    cudaEventRecord(evEnd, s2);
    cudaStreamWaitEvent(0, evEnd, 0);  // rejoin before capture ends

    cudaEventDestroy(evFork);
    cudaEventDestroy(evCSR);
    cudaEventDestroy(evS1);
    cudaEventDestroy(evG2);
    cudaEventDestroy(evS2);
    cudaEventDestroy(evG3);
    cudaEventDestroy(evS3f);
    cudaEventDestroy(evEnd);
    cudaStreamDestroy(s2);
}

// round 11
// speedup vs baseline: 1.0461x; 1.0461x over previous
#include <cuda_runtime.h>
#include <cuda_bf16.h>
#include <math.h>
#include <stdint.h>

#define NN 50000
#define NE 800000

// ---------------- scratch (device globals; allocation-free rule) -----------
__device__ float g_bufA[NN * 64];
__device__ float g_bufB[NN * 64];
__device__ int   g_cnt[NN];
__device__ int   g_start[NN];
__device__ int   g_rank[NE];
__device__ int   g_total;
__device__ int2  g_edge[NE];   // packed (col, weight-bits)

// ---------------------------------------------------------------------------
// CSR build. hist stores each edge's within-row rank (atomicAdd return),
// so scatter needs NO atomics — just start[row]+rank.
// ---------------------------------------------------------------------------
__global__ void zero_cnt_kernel() {
    int i = blockIdx.x * blockDim.x + threadIdx.x;
    if (i < NN) g_cnt[i] = 0;
    if (i == 0) g_total = 0;
}

__global__ void hist_rank_kernel(const int* __restrict__ row) {
    int e = blockIdx.x * blockDim.x + threadIdx.x;
    if (e < NE) g_rank[e] = atomicAdd(&g_cnt[row[e]], 1);
}

__global__ __launch_bounds__(256) void offsets_kernel() {
    __shared__ int sp[256];
    __shared__ int base;
    const int t = threadIdx.x;
    const int r = blockIdx.x * 256 + t;
    int c = (r < NN) ? g_cnt[r] : 0;
    sp[t] = c;
    __syncthreads();
    #pragma unroll
    for (int off = 1; off < 256; off <<= 1) {
        int v = (t >= off) ? sp[t - off] : 0;
        __syncthreads();
        sp[t] += v;
        __syncthreads();
    }
    if (t == 255) base = atomicAdd(&g_total, sp[255]);
    __syncthreads();
    if (r < NN) g_start[r] = base + sp[t] - c;
}

// atomic-free scatter: coalesced reads, one random 8B store per edge
__global__ void scatter_kernel(const int* __restrict__ row,
                               const int* __restrict__ col,
                               const float* __restrict__ ew) {
    int e = blockIdx.x * blockDim.x + threadIdx.x;
    if (e < NE) {
        int p = g_start[row[e]] + g_rank[e];
        g_edge[p] = make_int2(col[e], __float_as_int(ew[e]));
    }
}

// ---------------------------------------------------------------------------
// SpMM via CSR, warp per row, MLP-4 edge batching.
// NF2 = feature float2s per row (32 for D=64, 20 for D=40).
// LOGSM: fuse log-softmax over D=40 into the epilogue (writes final output).
// ---------------------------------------------------------------------------
template <int NF2, bool LOGSM>
__global__ __launch_bounds__(256) void spmm_csr_kernel(
    const float2* __restrict__ sup, float2* __restrict__ out)
{
    int warp = (blockIdx.x * blockDim.x + threadIdx.x) >> 5;
    if (warp >= NN) return;
    const int lane = threadIdx.x & 31;
    const bool act = (NF2 == 32) || (lane < NF2);
    int s = g_start[warp];
    int e = s + g_cnt[warp];

    float2 acc = make_float2(0.f, 0.f);
    int i = s;
    for (; i + 4 <= e; i += 4) {
        int2 c0 = g_edge[i + 0];
        int2 c1 = g_edge[i + 1];
        int2 c2 = g_edge[i + 2];
        int2 c3 = g_edge[i + 3];
        if (act) {
            float2 v0 = sup[(size_t)c0.x * NF2 + lane];
            float2 v1 = sup[(size_t)c1.x * NF2 + lane];
            float2 v2 = sup[(size_t)c2.x * NF2 + lane];
            float2 v3 = sup[(size_t)c3.x * NF2 + lane];
            float w0 = __int_as_float(c0.y), w1 = __int_as_float(c1.y);
            float w2 = __int_as_float(c2.y), w3 = __int_as_float(c3.y);
            acc.x = fmaf(v0.x, w0, acc.x); acc.y = fmaf(v0.y, w0, acc.y);
            acc.x = fmaf(v1.x, w1, acc.x); acc.y = fmaf(v1.y, w1, acc.y);
            acc.x = fmaf(v2.x, w2, acc.x); acc.y = fmaf(v2.y, w2, acc.y);
            acc.x = fmaf(v3.x, w3, acc.x); acc.y = fmaf(v3.y, w3, acc.y);
        }
    }
    for (; i < e; i++) {
        int2 c = g_edge[i];
        if (act) {
            float2 v = sup[(size_t)c.x * NF2 + lane];
            float ww = __int_as_float(c.y);
            acc.x = fmaf(v.x, ww, acc.x);
            acc.y = fmaf(v.y, ww, acc.y);
        }
    }

    if (!LOGSM) {
        if (act) out[(size_t)warp * NF2 + lane] = acc;
    } else {
        float mv = act ? fmaxf(acc.x, acc.y) : -INFINITY;
        #pragma unroll
        for (int o = 16; o; o >>= 1) mv = fmaxf(mv, __shfl_xor_sync(0xffffffffu, mv, o));
        float sv = act ? (expf(acc.x - mv) + expf(acc.y - mv)) : 0.f;
        #pragma unroll
        for (int o = 16; o; o >>= 1) sv += __shfl_xor_sync(0xffffffffu, sv, o);
        float ls = mv + logf(sv);
        if (act) out[(size_t)warp * NF2 + lane] = make_float2(acc.x - ls, acc.y - ls);
    }
}

// ---------------------------------------------------------------------------
// Split-bf16 tensor-core GEMM (rel_err ~2e-6)
// ---------------------------------------------------------------------------
#define SROW 24

__device__ __forceinline__ unsigned pack_bf16(float a, float b) {
    __nv_bfloat162 t = __floats2bfloat162_rn(a, b);
    return *reinterpret_cast<unsigned*>(&t);
}

__device__ __forceinline__ void mma16816(float* c, const unsigned* a, const unsigned* b) {
    asm volatile(
        "mma.sync.aligned.m16n8k16.row.col.f32.bf16.bf16.f32 "
        "{%0,%1,%2,%3}, {%4,%5,%6,%7}, {%8,%9}, {%0,%1,%2,%3};"
        : "+f"(c[0]), "+f"(c[1]), "+f"(c[2]), "+f"(c[3])
        : "r"(a[0]), "r"(a[1]), "r"(a[2]), "r"(a[3]), "r"(b[0]), "r"(b[1]));
}

template <bool RELU>
__global__ __launch_bounds__(256) void gemm_mma_kernel(
    const float* __restrict__ A, const float* __restrict__ B,
    const float* __restrict__ bias, float* __restrict__ C,
    int M, int K, int N)
{
    __shared__ __nv_bfloat16 Ah[2][128 * SROW], Al[2][128 * SROW];
    __shared__ __nv_bfloat16 Bh[2][64 * SROW],  Bl[2][64 * SROW];

    const int tid  = threadIdx.x;
    const int m0   = blockIdx.x * 128;
    const int wid  = tid >> 5;
    const int lane = tid & 31;
    const int wm = (wid & 3) * 32;
    const int wn = (wid >> 2) * 32;
    const int qm = lane >> 2;
    const int qk = lane & 3;

    const int arow = tid >> 1;
    const int akh  = (tid & 1) * 8;
    const bool aok = (m0 + arow) < M;
    const float* Aptr = A + (size_t)(m0 + arow) * K + akh;

    const int bk = tid >> 4;
    const int bn = (tid * 4) & 63;

    float av[8];
    float bv[4];
    float acc[2][4][4] = {};

    const int S = K / 16;

    auto load_regs = [&](int k0) {
        if (aok) {
            float4 v0 = *reinterpret_cast<const float4*>(Aptr + k0);
            float4 v1 = *reinterpret_cast<const float4*>(Aptr + k0 + 4);
            av[0] = v0.x; av[1] = v0.y; av[2] = v0.z; av[3] = v0.w;
            av[4] = v1.x; av[5] = v1.y; av[6] = v1.z; av[7] = v1.w;
            if (RELU) {
                #pragma unroll
                for (int i = 0; i < 8; i++) av[i] = fmaxf(av[i], 0.f);
            }
        } else {
            #pragma unroll
            for (int i = 0; i < 8; i++) av[i] = 0.f;
        }
        #pragma unroll
        for (int j = 0; j < 4; j++) {
            int n = bn + j;
            bv[j] = (n < N) ? B[(size_t)(k0 + bk) * N + n] : 0.f;
        }
    };

    auto store_stage = [&](int st) {
        float lo[8];
        unsigned h[4], l[4];
        #pragma unroll
        for (int i = 0; i < 8; i++) {
            __nv_bfloat16 hb = __float2bfloat16_rn(av[i]);
            lo[i] = av[i] - __bfloat162float(hb);
        }
        #pragma unroll
        for (int p = 0; p < 4; p++) {
            h[p] = pack_bf16(av[2 * p], av[2 * p + 1]);
            l[p] = pack_bf16(lo[2 * p], lo[2 * p + 1]);
        }
        *reinterpret_cast<uint4*>(&Ah[st][arow * SROW + akh]) = make_uint4(h[0], h[1], h[2], h[3]);
        *reinterpret_cast<uint4*>(&Al[st][arow * SROW + akh]) = make_uint4(l[0], l[1], l[2], l[3]);
        #pragma unroll
        for (int j = 0; j < 4; j++) {
            __nv_bfloat16 hb = __float2bfloat16_rn(bv[j]);
            float lf = bv[j] - __bfloat162float(hb);
            Bh[st][(bn + j) * SROW + bk] = hb;
            Bl[st][(bn + j) * SROW + bk] = __float2bfloat16_rn(lf);
        }
    };

    load_regs(0);
    store_stage(0);
    __syncthreads();

    for (int s = 0; s < S; s++) {
        const int cur = s & 1;
        if (s + 1 < S) load_regs((s + 1) * 16);

        unsigned ah[2][4], al[2][4], bh[4][2], bl[4][2];
        #pragma unroll
        for (int i = 0; i < 2; i++) {
            int r = (wm + i * 16 + qm) * SROW;
            ah[i][0] = *reinterpret_cast<unsigned*>(&Ah[cur][r + qk * 2]);
            ah[i][1] = *reinterpret_cast<unsigned*>(&Ah[cur][r + 8 * SROW + qk * 2]);
            ah[i][2] = *reinterpret_cast<unsigned*>(&Ah[cur][r + 8 + qk * 2]);
            ah[i][3] = *reinterpret_cast<unsigned*>(&Ah[cur][r + 8 * SROW + 8 + qk * 2]);
            al[i][0] = *reinterpret_cast<unsigned*>(&Al[cur][r + qk * 2]);
            al[i][1] = *reinterpret_cast<unsigned*>(&Al[cur][r + 8 * SROW + qk * 2]);
            al[i][2] = *reinterpret_cast<unsigned*>(&Al[cur][r + 8 + qk * 2]);
            al[i][3] = *reinterpret_cast<unsigned*>(&Al[cur][r + 8 * SROW + 8 + qk * 2]);
        }
        #pragma unroll
        for (int j = 0; j < 4; j++) {
            int r = (wn + j * 8 + qm) * SROW;
            bh[j][0] = *reinterpret_cast<unsigned*>(&Bh[cur][r + qk * 2]);
            bh[j][1] = *reinterpret_cast<unsigned*>(&Bh[cur][r + 8 + qk * 2]);
            bl[j][0] = *reinterpret_cast<unsigned*>(&Bl[cur][r + qk * 2]);
            bl[j][1] = *reinterpret_cast<unsigned*>(&Bl[cur][r + 8 + qk * 2]);
        }

        #pragma unroll
        for (int i = 0; i < 2; i++)
            #pragma unroll
            for (int j = 0; j < 4; j++) {
                mma16816(acc[i][j], ah[i], bh[j]);
                mma16816(acc[i][j], ah[i], bl[j]);
                mma16816(acc[i][j], al[i], bh[j]);
            }

        if (s + 1 < S) {
            store_stage(cur ^ 1);
            __syncthreads();
        }
    }

    #pragma unroll
    for (int j = 0; j < 4; j++) {
        int c0 = wn + j * 8 + (lane & 3) * 2;
        if (c0 >= N) continue;
        float b0 = bias[c0], b1 = bias[c0 + 1];
        #pragma unroll
        for (int i = 0; i < 2; i++) {
            int r0 = m0 + wm + i * 16 + (lane >> 2);
            if (r0 < M) {
                float2 o = make_float2(acc[i][j][0] + b0, acc[i][j][1] + b1);
                *reinterpret_cast<float2*>(C + (size_t)r0 * N + c0) = o;
            }
            if (r0 + 8 < M) {
                float2 o = make_float2(acc[i][j][2] + b0, acc[i][j][3] + b1);
                *reinterpret_cast<float2*>(C + (size_t)(r0 + 8) * N + c0) = o;
            }
        }
    }
}

// ---------------------------------------------------------------------------
// launch: R7 structure (CSR build ∥ GEMM1, then serial layers).
// Buffers: gemm1->A ; spmm1 A->B ; gemm2 B->A ; spmm2 A->B ; gemm3 B->A ;
// spmm3+lsm A->out.
// ---------------------------------------------------------------------------
extern "C" void kernel_launch(void* const* d_in, const int* in_sizes, int n_in,
                              void* d_out, int out_size)
{
    const float* x   = (const float*)d_in[0];
    const float* ew  = (const float*)d_in[1];
    const float* W1  = (const float*)d_in[2];
    const float* b1  = (const float*)d_in[3];
    const float* W2  = (const float*)d_in[4];
    const float* b2  = (const float*)d_in[5];
    const float* W3  = (const float*)d_in[6];
    const float* b3  = (const float*)d_in[7];
    const int*   row = (const int*)d_in[8];
    const int*   col = (const int*)d_in[9];
    float* out = (float*)d_out;

    float *bufA, *bufB;
    cudaGetSymbolAddress((void**)&bufA, g_bufA);
    cudaGetSymbolAddress((void**)&bufB, g_bufB);

    const int gemmBlocks = (NN + 127) / 128;          // 391
    const int edgeBlocks = (NE + 255) / 256;          // 3125
    const int rowBlocks  = (NN + 255) / 256;          // 196
    const int rowWarpBlocks = (NN * 32 + 255) / 256;  // 6250

    cudaStream_t s2;
    cudaStreamCreate(&s2);
    cudaEvent_t evFork, evCSR;
    cudaEventCreateWithFlags(&evFork, cudaEventDisableTiming);
    cudaEventCreateWithFlags(&evCSR,  cudaEventDisableTiming);

    cudaEventRecord(evFork, 0);
    cudaStreamWaitEvent(s2, evFork, 0);

    // s2: CSR build (concurrent with GEMM1 on main)
    zero_cnt_kernel<<<rowBlocks, 256, 0, s2>>>();
    hist_rank_kernel<<<edgeBlocks, 256, 0, s2>>>(row);
    offsets_kernel<<<rowBlocks, 256, 0, s2>>>();
    scatter_kernel<<<edgeBlocks, 256, 0, s2>>>(row, col, ew);
    cudaEventRecord(evCSR, s2);

    // main: GEMM1 -> A
    gemm_mma_kernel<false><<<gemmBlocks, 256>>>(x, W1, b1, bufA, NN, 512, 64);
    cudaStreamWaitEvent(0, evCSR, 0);

    // layer 1
    spmm_csr_kernel<32, false><<<rowWarpBlocks, 256>>>((const float2*)bufA, (float2*)bufB);
    // layer 2
    gemm_mma_kernel<true><<<gemmBlocks, 256>>>(bufB, W2, b2, bufA, NN, 64, 64);
    spmm_csr_kernel<32, false><<<rowWarpBlocks, 256>>>((const float2*)bufA, (float2*)bufB);
    // layer 3 + fused log-softmax
    gemm_mma_kernel<false><<<gemmBlocks, 256>>>(bufB, W3, b3, bufA, NN, 64, 40);
    spmm_csr_kernel<20, true><<<rowWarpBlocks, 256>>>((const float2*)bufA, (float2*)out);

    cudaEventDestroy(evFork);
    cudaEventDestroy(evCSR);
    cudaStreamDestroy(s2);
}